// round 4
// baseline (speedup 1.0000x reference)
#include <cuda_runtime.h>
#include <cstdint>

#define NN 100000
#define EE 1600000
#define EAD 7
#define HD 64
#define LD 32
#define GG 512
#define CC 6

// -------- scratch (device globals; no allocations allowed) --------
__device__ __align__(16) float g_agg1[NN];
__device__ __align__(16) float g_h1[(size_t)NN * HD];
__device__ __align__(16) float g_agg2[(size_t)NN * HD];
__device__ __align__(16) float g_h2[(size_t)NN * HD];
__device__ __align__(16) float g_noise[(size_t)NN * LD];
__device__ __align__(16) float g_zsum[GG * LD];
__device__ __align__(16) float g_cnt[GG];

// ============== zero-init scratch (kernel; memset nodes on device
//                symbols are not graph-capturable) ==============
__global__ void k_zero() {
    int i = blockIdx.x * blockDim.x + threadIdx.x;
    const float4 z4 = make_float4(0.f, 0.f, 0.f, 0.f);
    if (i < NN * HD / 4) {
        reinterpret_cast<float4*>(g_agg2)[i] = z4;
        if (i < NN / 4) reinterpret_cast<float4*>(g_agg1)[i] = z4;
        if (i < GG * LD / 4) reinterpret_cast<float4*>(g_zsum)[i] = z4;
        if (i < GG / 4) reinterpret_cast<float4*>(g_cnt)[i] = z4;
    }
}

// ================= conv1 edge pass: scalar messages =================
// NOTE: edge_index/batch are int32 (JAX x64 disabled downcasts jnp.int64).
__global__ void k_edge1(const float* __restrict__ x, const int* __restrict__ ei,
                        const float* __restrict__ ea, const float* __restrict__ We1,
                        const float* __restrict__ be1) {
    int e = blockIdx.x * blockDim.x + threadIdx.x;
    if (e >= EE) return;
    int s = ei[e];
    int d = ei[EE + e];
    float acc = be1[0];
#pragma unroll
    for (int j = 0; j < EAD; j++) acc = fmaf(ea[(size_t)e * EAD + j], We1[j], acc);
    acc += x[s];
    acc = fmaxf(acc, 0.0f);
    atomicAdd(&g_agg1[d], acc);
}

// ================= conv1 node MLP: scalar -> 64 -> 64 =================
__global__ void k_node1(const float* __restrict__ x, const float* __restrict__ W11,
                        const float* __restrict__ b11, const float* __restrict__ W12,
                        const float* __restrict__ b12, const float* __restrict__ eps1) {
    __shared__ float sW[HD * HD];
    __shared__ float sb[HD];
    __shared__ float st[4][HD];
    int tid = threadIdx.x;
    for (int i = tid; i < HD * HD; i += 256) sW[i] = W12[i];
    if (tid < HD) sb[tid] = b12[tid];
    int nl = tid >> 6;
    int lane = tid & 63;
    int node = blockIdx.x * 4 + nl;
    float s = (1.0f + eps1[0]) * x[node] + g_agg1[node];
    st[nl][lane] = fmaxf(fmaf(s, W11[lane], b11[lane]), 0.0f);
    __syncthreads();
    float acc = sb[lane];
#pragma unroll
    for (int j = 0; j < HD; j++) acc = fmaf(st[nl][j], sW[j * HD + lane], acc);
    g_h1[(size_t)node * HD + lane] = fmaxf(acc, 0.0f);
}

// ======== conv2 edge pass: 16 lanes/edge, atomic scatter ========
__global__ void k_edge2(const int* __restrict__ ei, const float* __restrict__ ea,
                        const float* __restrict__ We2, const float* __restrict__ be2) {
    __shared__ float sW[EAD * HD];
    __shared__ float sb[HD];
    int tid = threadIdx.x;
    for (int i = tid; i < EAD * HD; i += 256) sW[i] = We2[i];
    if (tid < HD) sb[tid] = be2[tid];
    __syncthreads();
    int gwarp = (blockIdx.x * 256 + tid) >> 5;     // 8 warps/block, 2 edges/warp
    int lane = tid & 31;
    int half = lane >> 4;
    int l = lane & 15;
    int e = gwarp * 2 + half;                      // grid exactly covers EE
    int s = ei[e];
    int d = ei[EE + e];
    float av = (l < EAD) ? ea[(size_t)e * EAD + l] : 0.0f;
    int c = l * 4;
    float4 acc = make_float4(sb[c], sb[c + 1], sb[c + 2], sb[c + 3]);
#pragma unroll
    for (int j = 0; j < EAD; j++) {
        float a = __shfl_sync(0xffffffffu, av, half * 16 + j);
        const float* w = &sW[j * HD + c];
        acc.x = fmaf(a, w[0], acc.x);
        acc.y = fmaf(a, w[1], acc.y);
        acc.z = fmaf(a, w[2], acc.z);
        acc.w = fmaf(a, w[3], acc.w);
    }
    const float4 hv = *reinterpret_cast<const float4*>(&g_h1[(size_t)s * HD + c]);
    float* p = &g_agg2[(size_t)d * HD + c];
    atomicAdd(p + 0, fmaxf(hv.x + acc.x, 0.0f));
    atomicAdd(p + 1, fmaxf(hv.y + acc.y, 0.0f));
    atomicAdd(p + 2, fmaxf(hv.z + acc.z, 0.0f));
    atomicAdd(p + 3, fmaxf(hv.w + acc.w, 0.0f));
}

// ================= conv2 node MLP: 64 -> 64 -> 64 =================
__global__ void k_node2(const float* __restrict__ W21, const float* __restrict__ b21,
                        const float* __restrict__ W22, const float* __restrict__ b22,
                        const float* __restrict__ eps2) {
    __shared__ float sW1[HD * HD];
    __shared__ float sW2[HD * HD];
    __shared__ float sa[4][HD];
    __shared__ float su[4][HD];
    int tid = threadIdx.x;
    for (int i = tid; i < HD * HD; i += 256) { sW1[i] = W21[i]; sW2[i] = W22[i]; }
    int nl = tid >> 6;
    int lane = tid & 63;
    int node = blockIdx.x * 4 + nl;
    size_t base = (size_t)node * HD + lane;
    sa[nl][lane] = (1.0f + eps2[0]) * g_h1[base] + g_agg2[base];
    __syncthreads();
    float acc = b21[lane];
#pragma unroll
    for (int i = 0; i < HD; i++) acc = fmaf(sa[nl][i], sW1[i * HD + lane], acc);
    su[nl][lane] = fmaxf(acc, 0.0f);
    __syncthreads();
    acc = b22[lane];
#pragma unroll
    for (int j = 0; j < HD; j++) acc = fmaf(su[nl][j], sW2[j * HD + lane], acc);
    g_h2[base] = fmaxf(acc, 0.0f);
}

// ===== JAX threefry2x32 noise, PARTITIONABLE counter scheme =====
// (jax_threefry_partitionable=True default: per-element uint64 counter i,
//  block = (hi32(i), lo32(i)) = (0, i); 32-bit bits = out0 ^ out1)
__device__ __forceinline__ float bits_to_normal(uint32_t bits) {
    // jax uniform(nextafter(-1,0), 1) then sqrt(2)*erfinv (XLA Giles poly)
    float f = __uint_as_float((bits >> 9) | 0x3f800000u) - 1.0f;
    const float lo = -0.99999994f;            // nextafterf(-1,0)
    float u = fmaf(f, 2.0f, lo);              // maxval-minval rounds to 2.0f
    u = fmaxf(u, lo);
    float w = -log1pf(-u * u);
    float p;
    if (w < 5.0f) {
        w -= 2.5f;
        p = 2.81022636e-08f;
        p = fmaf(p, w, 3.43273939e-07f);
        p = fmaf(p, w, -3.5233877e-06f);
        p = fmaf(p, w, -4.39150654e-06f);
        p = fmaf(p, w, 0.00021858087f);
        p = fmaf(p, w, -0.00125372503f);
        p = fmaf(p, w, -0.00417768164f);
        p = fmaf(p, w, 0.246640727f);
        p = fmaf(p, w, 1.50140941f);
    } else {
        w = sqrtf(w) - 3.0f;
        p = -0.000200214257f;
        p = fmaf(p, w, 0.000100950558f);
        p = fmaf(p, w, 0.00134934322f);
        p = fmaf(p, w, -0.00367342844f);
        p = fmaf(p, w, 0.00573950773f);
        p = fmaf(p, w, -0.0076224613f);
        p = fmaf(p, w, 0.00943887047f);
        p = fmaf(p, w, 1.00167406f);
        p = fmaf(p, w, 2.83297682f);
    }
    return 1.41421356237f * (p * u);
}

#define TF_ROUND(r) { x0 += x1; x1 = (x1 << (r)) | (x1 >> (32 - (r))); x1 ^= x0; }

__global__ void k_noise() {
    int i = blockIdx.x * blockDim.x + threadIdx.x;
    if (i >= NN * LD) return;
    uint32_t x0 = 0u;                 // hi32 of uint64 counter (size < 2^32)
    uint32_t x1 = (uint32_t)i;        // lo32
    const uint32_t k0 = 0u, k1 = 42u;
    const uint32_t k2 = 0x1BD11BDAu ^ k0 ^ k1;
    x0 += k0; x1 += k1;
    TF_ROUND(13) TF_ROUND(15) TF_ROUND(26) TF_ROUND(6)
    x0 += k1; x1 += k2 + 1u;
    TF_ROUND(17) TF_ROUND(29) TF_ROUND(16) TF_ROUND(24)
    x0 += k2; x1 += k0 + 2u;
    TF_ROUND(13) TF_ROUND(15) TF_ROUND(26) TF_ROUND(6)
    x0 += k0; x1 += k1 + 3u;
    TF_ROUND(17) TF_ROUND(29) TF_ROUND(16) TF_ROUND(24)
    x0 += k1; x1 += k2 + 4u;
    TF_ROUND(13) TF_ROUND(15) TF_ROUND(26) TF_ROUND(6)
    x0 += k2; x1 += k0 + 5u;
    g_noise[i] = bits_to_normal(x0 ^ x1);   // 32-bit combine: xor of the pair
}

// ========= heads: mu / logvar / z + pooled atomic accumulation =========
__global__ void k_heads(const int* __restrict__ batch,
                        const float* __restrict__ Wmu, const float* __restrict__ bmu,
                        const float* __restrict__ Wlv, const float* __restrict__ blv,
                        float* __restrict__ out) {
    __shared__ float sWm[HD * LD];
    __shared__ float sWl[HD * LD];
    __shared__ float sh[8][HD];
    int tid = threadIdx.x;
    for (int i = tid; i < HD * LD; i += 256) { sWm[i] = Wmu[i]; sWl[i] = Wlv[i]; }
    int nl = tid >> 5;
    int l = tid & 31;
    int node = blockIdx.x * 8 + nl;
    sh[nl][l] = g_h2[(size_t)node * HD + l];
    sh[nl][l + 32] = g_h2[(size_t)node * HD + l + 32];
    __syncthreads();
    float mu = bmu[l], lv = blv[l];
#pragma unroll
    for (int k = 0; k < HD; k++) {
        float hk = sh[nl][k];
        mu = fmaf(hk, sWm[k * LD + l], mu);
        lv = fmaf(hk, sWl[k * LD + l], lv);
    }
    float nz = g_noise[(size_t)node * LD + l];
    float z = fmaf(nz, expf(0.5f * lv), mu);
    const size_t NL = (size_t)NN * LD;
    out[(size_t)node * LD + l] = z;
    out[NL + (size_t)node * LD + l] = mu;
    out[2 * NL + (size_t)node * LD + l] = lv;
    int g = batch[node];
    atomicAdd(&g_zsum[g * LD + l], z);
    if (l == 0) atomicAdd(&g_cnt[g], 1.0f);
}

// ================= classifier over graph embeddings =================
__global__ void k_logits(const float* __restrict__ Wc, const float* __restrict__ bc,
                         float* __restrict__ out) {
    int i = blockIdx.x * blockDim.x + threadIdx.x;
    if (i >= GG * CC) return;
    int g = i / CC, c = i % CC;
    float inv = 1.0f / fmaxf(g_cnt[g], 1.0f);
    float acc = bc[c];
#pragma unroll
    for (int l = 0; l < LD; l++) acc = fmaf(g_zsum[g * LD + l] * inv, Wc[l * CC + c], acc);
    out[3 * (size_t)NN * LD + i] = acc;
}

// =========================== launcher ===========================
extern "C" void kernel_launch(void* const* d_in, const int* in_sizes, int n_in,
                              void* d_out, int out_size) {
    const float* x     = (const float*)d_in[0];
    const int*   ei    = (const int*)d_in[1];      // int32! (JAX x64 disabled)
    const float* ea    = (const float*)d_in[2];
    const int*   batch = (const int*)d_in[3];      // int32!
    const float* We1 = (const float*)d_in[4];
    const float* be1 = (const float*)d_in[5];
    const float* W11 = (const float*)d_in[6];
    const float* b11 = (const float*)d_in[7];
    const float* W12 = (const float*)d_in[8];
    const float* b12 = (const float*)d_in[9];
    const float* eps1 = (const float*)d_in[10];
    const float* We2 = (const float*)d_in[11];
    const float* be2 = (const float*)d_in[12];
    const float* W21 = (const float*)d_in[13];
    const float* b21 = (const float*)d_in[14];
    const float* W22 = (const float*)d_in[15];
    const float* b22 = (const float*)d_in[16];
    const float* eps2 = (const float*)d_in[17];
    const float* Wmu = (const float*)d_in[18];
    const float* bmu = (const float*)d_in[19];
    const float* Wlv = (const float*)d_in[20];
    const float* blv = (const float*)d_in[21];
    const float* Wc  = (const float*)d_in[22];
    const float* bc  = (const float*)d_in[23];
    float* out = (float*)d_out;

    k_zero<<<(NN * HD / 4 + 255) / 256, 256>>>();
    k_noise<<<(NN * LD + 255) / 256, 256>>>();
    k_edge1<<<EE / 256, 256>>>(x, ei, ea, We1, be1);
    k_node1<<<NN / 4, 256>>>(x, W11, b11, W12, b12, eps1);
    k_edge2<<<EE / 16, 256>>>(ei, ea, We2, be2);
    k_node2<<<NN / 4, 256>>>(W21, b21, W22, b22, eps2);
    k_heads<<<NN / 8, 256>>>(batch, Wmu, bmu, Wlv, blv, out);
    k_logits<<<(GG * CC + 255) / 256, 256>>>(Wc, bc, out);
}

// round 7
// speedup vs baseline: 1.7098x; 1.7098x over previous
#include <cuda_runtime.h>
#include <cstdint>

#define NN 100000
#define EE 1600000
#define EAD 7
#define HD 64
#define LD 32
#define GG 512
#define CC 6
#define NPB 64   // nodes per block in node MLP kernels
#define NG 8     // node subgroup size

// -------- scratch (device globals; no allocations allowed) --------
__device__ __align__(16) float g_agg1[NN];
__device__ __align__(16) float g_h1[(size_t)NN * HD];
__device__ __align__(16) float g_agg2[(size_t)NN * HD];
__device__ __align__(16) float g_noise[(size_t)NN * LD];
__device__ __align__(16) float g_zsum[GG * LD];
__device__ __align__(16) float g_cnt[GG];
__device__ __align__(16) float g_h2[(size_t)NN * HD];

// ============== zero-init scratch ==============
__global__ void k_zero() {
    int i = blockIdx.x * blockDim.x + threadIdx.x;
    const float4 z4 = make_float4(0.f, 0.f, 0.f, 0.f);
    if (i < NN * HD / 4) {
        reinterpret_cast<float4*>(g_agg2)[i] = z4;
        if (i < NN / 4) reinterpret_cast<float4*>(g_agg1)[i] = z4;
        if (i < GG * LD / 4) reinterpret_cast<float4*>(g_zsum)[i] = z4;
        if (i < GG / 4) reinterpret_cast<float4*>(g_cnt)[i] = z4;
    }
}

// ================= conv1 edge pass: scalar messages =================
__global__ void k_edge1(const float* __restrict__ x, const int* __restrict__ ei,
                        const float* __restrict__ ea, const float* __restrict__ We1,
                        const float* __restrict__ be1) {
    int e = blockIdx.x * blockDim.x + threadIdx.x;
    if (e >= EE) return;
    int s = ei[e];
    int d = ei[EE + e];
    float acc = be1[0];
#pragma unroll
    for (int j = 0; j < EAD; j++) acc = fmaf(ea[(size_t)e * EAD + j], We1[j], acc);
    acc += x[s];
    acc = fmaxf(acc, 0.0f);
    atomicAdd(&g_agg1[d], acc);
}

// ====== conv1 node MLP: register-weight scheme (scalar->64->64) ======
__global__ void k_node1(const float* __restrict__ x, const float* __restrict__ W11,
                        const float* __restrict__ b11, const float* __restrict__ W12,
                        const float* __restrict__ b12, const float* __restrict__ eps1) {
    __shared__ __align__(16) float st[NG][HD];
    __shared__ float sp[NG][4][HD];
    __shared__ float sw11[HD], sb1[HD], sb2[HD];
    int tid = threadIdx.x;
    int nl = tid >> 6, lane = tid & 63;
    float Wr[16];
#pragma unroll
    for (int k = 0; k < 16; k++) Wr[k] = W12[(nl * 16 + k) * HD + lane];
    if (tid < HD) { sw11[tid] = W11[tid]; sb1[tid] = b11[tid]; sb2[tid] = b12[tid]; }
    float ep = 1.0f + eps1[0];
    __syncthreads();                 // preamble stores visible to all warps
    int base = blockIdx.x * NPB;
    for (int g = 0; g < NPB / NG; g++) {
        int nb = base + g * NG;
        // phase A: first layer (rank-1) into shared
#pragma unroll
        for (int r = 0; r < 2; r++) {
            int id = tid + r * 256;
            int n = id >> 6, j = id & 63;
            int node = nb + n;
            float s = 0.0f;
            if (node < NN) s = ep * x[node] + g_agg1[node];
            st[n][j] = fmaxf(fmaf(s, sw11[j], sb1[j]), 0.0f);
        }
        __syncthreads();
        // phase B: partial dot with register weights (broadcast LDS.128)
#pragma unroll
        for (int n = 0; n < NG; n++) {
            const float4* a4 = reinterpret_cast<const float4*>(&st[n][nl * 16]);
            float acc = 0.0f;
#pragma unroll
            for (int q = 0; q < 4; q++) {
                float4 a = a4[q];
                acc = fmaf(a.x, Wr[q * 4 + 0], acc);
                acc = fmaf(a.y, Wr[q * 4 + 1], acc);
                acc = fmaf(a.z, Wr[q * 4 + 2], acc);
                acc = fmaf(a.w, Wr[q * 4 + 3], acc);
            }
            sp[n][nl][lane] = acc;
        }
        __syncthreads();
        // phase C: reduce + bias + relu + store
#pragma unroll
        for (int r = 0; r < 2; r++) {
            int id = tid + r * 256;
            int n = id >> 6, j = id & 63;
            int node = nb + n;
            if (node < NN) {
                float v = sp[n][0][j] + sp[n][1][j] + sp[n][2][j] + sp[n][3][j] + sb2[j];
                g_h1[(size_t)node * HD + j] = fmaxf(v, 0.0f);
            }
        }
        __syncthreads();
    }
}

// ======== conv2 edge pass: 16 lanes/edge, vector red scatter ========
__global__ void k_edge2(const int* __restrict__ ei, const float* __restrict__ ea,
                        const float* __restrict__ We2, const float* __restrict__ be2) {
    __shared__ float sW[EAD * HD];
    __shared__ float sb[HD];
    int tid = threadIdx.x;
    for (int i = tid; i < EAD * HD; i += 256) sW[i] = We2[i];
    if (tid < HD) sb[tid] = be2[tid];
    __syncthreads();
    int gwarp = (blockIdx.x * 256 + tid) >> 5;     // 2 edges/warp
    int lane = tid & 31;
    int half = lane >> 4;
    int l = lane & 15;
    int e = gwarp * 2 + half;                      // grid exactly covers EE
    int s = ei[e];
    int d = ei[EE + e];
    float av = (l < EAD) ? ea[(size_t)e * EAD + l] : 0.0f;
    int c = l * 4;
    float4 acc = make_float4(sb[c], sb[c + 1], sb[c + 2], sb[c + 3]);
#pragma unroll
    for (int j = 0; j < EAD; j++) {
        float a = __shfl_sync(0xffffffffu, av, half * 16 + j);
        const float* w = &sW[j * HD + c];
        acc.x = fmaf(a, w[0], acc.x);
        acc.y = fmaf(a, w[1], acc.y);
        acc.z = fmaf(a, w[2], acc.z);
        acc.w = fmaf(a, w[3], acc.w);
    }
    const float4 hv = *reinterpret_cast<const float4*>(&g_h1[(size_t)s * HD + c]);
    float mx = fmaxf(hv.x + acc.x, 0.0f);
    float my = fmaxf(hv.y + acc.y, 0.0f);
    float mz = fmaxf(hv.z + acc.z, 0.0f);
    float mw = fmaxf(hv.w + acc.w, 0.0f);
    float* p = &g_agg2[(size_t)d * HD + c];
    asm volatile("red.global.add.v4.f32 [%0], {%1,%2,%3,%4};"
                 :: "l"(p), "f"(mx), "f"(my), "f"(mz), "f"(mw) : "memory");
}

// ====== conv2 node MLP: register-weight scheme (64->64->64) ======
__global__ void k_node2(const float* __restrict__ W21, const float* __restrict__ b21,
                        const float* __restrict__ W22, const float* __restrict__ b22,
                        const float* __restrict__ eps2) {
    __shared__ __align__(16) float sa[NG][HD];
    __shared__ __align__(16) float su[NG][HD];
    __shared__ float sp[NG][4][HD];
    __shared__ float sb1[HD], sb2[HD];
    int tid = threadIdx.x;
    int nl = tid >> 6, lane = tid & 63;
    float W1r[16], W2r[16];
#pragma unroll
    for (int k = 0; k < 16; k++) {
        W1r[k] = W21[(nl * 16 + k) * HD + lane];
        W2r[k] = W22[(nl * 16 + k) * HD + lane];
    }
    if (tid < HD) { sb1[tid] = b21[tid]; sb2[tid] = b22[tid]; }
    float ep = 1.0f + eps2[0];
    __syncthreads();                 // preamble stores visible to all warps
    int base = blockIdx.x * NPB;
    for (int g = 0; g < NPB / NG; g++) {
        int nb = base + g * NG;
        // A: gather inputs
#pragma unroll
        for (int r = 0; r < 2; r++) {
            int id = tid + r * 256;
            int n = id >> 6, j = id & 63;
            int node = nb + n;
            float v = 0.0f;
            if (node < NN) {
                size_t o = (size_t)node * HD + j;
                v = ep * g_h1[o] + g_agg2[o];
            }
            sa[n][j] = v;
        }
        __syncthreads();
        // B1: layer-1 partials
#pragma unroll
        for (int n = 0; n < NG; n++) {
            const float4* a4 = reinterpret_cast<const float4*>(&sa[n][nl * 16]);
            float acc = 0.0f;
#pragma unroll
            for (int q = 0; q < 4; q++) {
                float4 a = a4[q];
                acc = fmaf(a.x, W1r[q * 4 + 0], acc);
                acc = fmaf(a.y, W1r[q * 4 + 1], acc);
                acc = fmaf(a.z, W1r[q * 4 + 2], acc);
                acc = fmaf(a.w, W1r[q * 4 + 3], acc);
            }
            sp[n][nl][lane] = acc;
        }
        __syncthreads();
        // C1: reduce -> relu -> su
#pragma unroll
        for (int r = 0; r < 2; r++) {
            int id = tid + r * 256;
            int n = id >> 6, j = id & 63;
            float v = sp[n][0][j] + sp[n][1][j] + sp[n][2][j] + sp[n][3][j] + sb1[j];
            su[n][j] = fmaxf(v, 0.0f);
        }
        __syncthreads();
        // B2: layer-2 partials
#pragma unroll
        for (int n = 0; n < NG; n++) {
            const float4* a4 = reinterpret_cast<const float4*>(&su[n][nl * 16]);
            float acc = 0.0f;
#pragma unroll
            for (int q = 0; q < 4; q++) {
                float4 a = a4[q];
                acc = fmaf(a.x, W2r[q * 4 + 0], acc);
                acc = fmaf(a.y, W2r[q * 4 + 1], acc);
                acc = fmaf(a.z, W2r[q * 4 + 2], acc);
                acc = fmaf(a.w, W2r[q * 4 + 3], acc);
            }
            sp[n][nl][lane] = acc;
        }
        __syncthreads();
        // C2: reduce -> relu -> h2
#pragma unroll
        for (int r = 0; r < 2; r++) {
            int id = tid + r * 256;
            int n = id >> 6, j = id & 63;
            int node = nb + n;
            if (node < NN) {
                float v = sp[n][0][j] + sp[n][1][j] + sp[n][2][j] + sp[n][3][j] + sb2[j];
                g_h2[(size_t)node * HD + j] = fmaxf(v, 0.0f);
            }
        }
        __syncthreads();
    }
}

// ===== JAX threefry2x32 noise, partitionable counter scheme =====
__device__ __forceinline__ float bits_to_normal(uint32_t bits) {
    float f = __uint_as_float((bits >> 9) | 0x3f800000u) - 1.0f;
    const float lo = -0.99999994f;
    float u = fmaf(f, 2.0f, lo);
    u = fmaxf(u, lo);
    float w = -log1pf(-u * u);
    float p;
    if (w < 5.0f) {
        w -= 2.5f;
        p = 2.81022636e-08f;
        p = fmaf(p, w, 3.43273939e-07f);
        p = fmaf(p, w, -3.5233877e-06f);
        p = fmaf(p, w, -4.39150654e-06f);
        p = fmaf(p, w, 0.00021858087f);
        p = fmaf(p, w, -0.00125372503f);
        p = fmaf(p, w, -0.00417768164f);
        p = fmaf(p, w, 0.246640727f);
        p = fmaf(p, w, 1.50140941f);
    } else {
        w = sqrtf(w) - 3.0f;
        p = -0.000200214257f;
        p = fmaf(p, w, 0.000100950558f);
        p = fmaf(p, w, 0.00134934322f);
        p = fmaf(p, w, -0.00367342844f);
        p = fmaf(p, w, 0.00573950773f);
        p = fmaf(p, w, -0.0076224613f);
        p = fmaf(p, w, 0.00943887047f);
        p = fmaf(p, w, 1.00167406f);
        p = fmaf(p, w, 2.83297682f);
    }
    return 1.41421356237f * (p * u);
}

#define TF_ROUND(r) { x0 += x1; x1 = (x1 << (r)) | (x1 >> (32 - (r))); x1 ^= x0; }

__global__ void k_noise() {
    int i = blockIdx.x * blockDim.x + threadIdx.x;
    if (i >= NN * LD) return;
    uint32_t x0 = 0u;
    uint32_t x1 = (uint32_t)i;
    const uint32_t k0 = 0u, k1 = 42u;
    const uint32_t k2 = 0x1BD11BDAu ^ k0 ^ k1;
    x0 += k0; x1 += k1;
    TF_ROUND(13) TF_ROUND(15) TF_ROUND(26) TF_ROUND(6)
    x0 += k1; x1 += k2 + 1u;
    TF_ROUND(17) TF_ROUND(29) TF_ROUND(16) TF_ROUND(24)
    x0 += k2; x1 += k0 + 2u;
    TF_ROUND(13) TF_ROUND(15) TF_ROUND(26) TF_ROUND(6)
    x0 += k0; x1 += k1 + 3u;
    TF_ROUND(17) TF_ROUND(29) TF_ROUND(16) TF_ROUND(24)
    x0 += k1; x1 += k2 + 4u;
    TF_ROUND(13) TF_ROUND(15) TF_ROUND(26) TF_ROUND(6)
    x0 += k2; x1 += k0 + 5u;
    g_noise[i] = bits_to_normal(x0 ^ x1);
}

// ========= heads: mu / logvar / z + pooled atomic accumulation =========
__global__ void k_heads(const int* __restrict__ batch,
                        const float* __restrict__ Wmu, const float* __restrict__ bmu,
                        const float* __restrict__ Wlv, const float* __restrict__ blv,
                        float* __restrict__ out) {
    __shared__ float sWm[HD * LD];
    __shared__ float sWl[HD * LD];
    __shared__ float sh[8][HD];
    int tid = threadIdx.x;
    for (int i = tid; i < HD * LD; i += 256) { sWm[i] = Wmu[i]; sWl[i] = Wlv[i]; }
    int nl = tid >> 5;
    int l = tid & 31;
    int node = blockIdx.x * 8 + nl;
    sh[nl][l] = g_h2[(size_t)node * HD + l];
    sh[nl][l + 32] = g_h2[(size_t)node * HD + l + 32];
    __syncthreads();
    float mu = bmu[l], lv = blv[l];
#pragma unroll
    for (int k = 0; k < HD; k++) {
        float hk = sh[nl][k];
        mu = fmaf(hk, sWm[k * LD + l], mu);
        lv = fmaf(hk, sWl[k * LD + l], lv);
    }
    float nz = g_noise[(size_t)node * LD + l];
    float z = fmaf(nz, expf(0.5f * lv), mu);
    const size_t NL = (size_t)NN * LD;
    out[(size_t)node * LD + l] = z;
    out[NL + (size_t)node * LD + l] = mu;
    out[2 * NL + (size_t)node * LD + l] = lv;
    int g = batch[node];
    atomicAdd(&g_zsum[g * LD + l], z);
    if (l == 0) atomicAdd(&g_cnt[g], 1.0f);
}

// ================= classifier over graph embeddings =================
__global__ void k_logits(const float* __restrict__ Wc, const float* __restrict__ bc,
                         float* __restrict__ out) {
    int i = blockIdx.x * blockDim.x + threadIdx.x;
    if (i >= GG * CC) return;
    int g = i / CC, c = i % CC;
    float inv = 1.0f / fmaxf(g_cnt[g], 1.0f);
    float acc = bc[c];
#pragma unroll
    for (int l = 0; l < LD; l++) acc = fmaf(g_zsum[g * LD + l] * inv, Wc[l * CC + c], acc);
    out[3 * (size_t)NN * LD + i] = acc;
}

// =========================== launcher ===========================
extern "C" void kernel_launch(void* const* d_in, const int* in_sizes, int n_in,
                              void* d_out, int out_size) {
    const float* x     = (const float*)d_in[0];
    const int*   ei    = (const int*)d_in[1];
    const float* ea    = (const float*)d_in[2];
    const int*   batch = (const int*)d_in[3];
    const float* We1 = (const float*)d_in[4];
    const float* be1 = (const float*)d_in[5];
    const float* W11 = (const float*)d_in[6];
    const float* b11 = (const float*)d_in[7];
    const float* W12 = (const float*)d_in[8];
    const float* b12 = (const float*)d_in[9];
    const float* eps1 = (const float*)d_in[10];
    const float* We2 = (const float*)d_in[11];
    const float* be2 = (const float*)d_in[12];
    const float* W21 = (const float*)d_in[13];
    const float* b21 = (const float*)d_in[14];
    const float* W22 = (const float*)d_in[15];
    const float* b22 = (const float*)d_in[16];
    const float* eps2 = (const float*)d_in[17];
    const float* Wmu = (const float*)d_in[18];
    const float* bmu = (const float*)d_in[19];
    const float* Wlv = (const float*)d_in[20];
    const float* blv = (const float*)d_in[21];
    const float* Wc  = (const float*)d_in[22];
    const float* bc  = (const float*)d_in[23];
    float* out = (float*)d_out;

    k_zero<<<(NN * HD / 4 + 255) / 256, 256>>>();
    k_noise<<<(NN * LD + 255) / 256, 256>>>();
    k_edge1<<<EE / 256, 256>>>(x, ei, ea, We1, be1);
    k_node1<<<(NN + NPB - 1) / NPB, 256>>>(x, W11, b11, W12, b12, eps1);
    k_edge2<<<EE / 16, 256>>>(ei, ea, We2, be2);
    k_node2<<<(NN + NPB - 1) / NPB, 256>>>(W21, b21, W22, b22, eps2);
    k_heads<<<NN / 8, 256>>>(batch, Wmu, bmu, Wlv, blv, out);
    k_logits<<<(GG * CC + 255) / 256, 256>>>(Wc, bc, out);
}